// round 5
// baseline (speedup 1.0000x reference)
#include <cuda_runtime.h>
#include <cuda_bf16.h>
#include <cuda_fp8.h>
#include <cstdint>
#include <cstddef>

// Problem constants
#define NROWS   65536
#define VDIM    1024
#define DDIM    256
#define M_TILE  64
#define NCTAS   (NROWS / M_TILE)     // 1024
#define NTHREADS 256
#define KCH     64
#define NCHUNK  (VDIM / KCH)         // 16
#define ASTRIDE_B 80                 // bytes per A smem row (64 fp8 + 16 pad)
#define BSTRIDE_B 80                 // bytes per B smem row
#define A_TILE_B (M_TILE * ASTRIDE_B)    // 5120
#define B_TILE_B (DDIM * BSTRIDE_B)      // 20480
#define SMEM_BYTES (2 * A_TILE_B + 2 * B_TILE_B)   // 51200

// Static scratch: codebook transposed+converted to fp8 e4m3, [D][V]
__device__ uint8_t g_cbT8[DDIM * VDIM];
__device__ int g_tgt64;

// ---------------------------------------------------------------------------
// Prep: transpose codebook fp32 [V][D] -> e4m3 [D][V]; zero out; dtype sniff.
// ---------------------------------------------------------------------------
__global__ void prep_kernel(const float* __restrict__ cb,
                            const void*  __restrict__ tgt,
                            float* __restrict__ out) {
    __shared__ float tile[32][33];
    int v0 = blockIdx.x * 32;
    int d0 = blockIdx.y * 32;
    int tx = threadIdx.x, ty = threadIdx.y;

    #pragma unroll
    for (int i = 0; i < 4; i++) {
        int v = ty + i * 8;
        tile[v][tx] = cb[(size_t)(v0 + v) * DDIM + d0 + tx];
    }
    __syncthreads();
    #pragma unroll
    for (int i = 0; i < 4; i++) {
        int d = ty + i * 8;
        g_cbT8[(size_t)(d0 + d) * VDIM + v0 + tx] =
            __nv_cvt_float_to_fp8(tile[tx][d], __NV_SATFINITE, __NV_E4M3);
    }

    if (blockIdx.x == 0 && blockIdx.y == 0 && tx == 0 && ty == 0) {
        const int* t = (const int*)tgt;
        int is64 = 1;
        for (int i = 0; i < 256; i++) {
            if (t[2 * i + 1] != 0) { is64 = 0; break; }
        }
        g_tgt64 = is64;
        out[0] = 0.0f;
    }
}

// ---------------------------------------------------------------------------
// Helpers
// ---------------------------------------------------------------------------
__device__ __forceinline__ uint32_t smem_u32(const void* p) {
    uint32_t a;
    asm("{ .reg .u64 t; cvta.to.shared.u64 t, %1; cvt.u32.u64 %0, t; }" : "=r"(a) : "l"(p));
    return a;
}

__device__ __forceinline__ void cp16(uint32_t dst_smem, const void* src_gmem) {
    asm volatile("cp.async.cg.shared.global [%0], [%1], 16;" :: "r"(dst_smem), "l"(src_gmem));
}

__device__ __forceinline__ void ldsm_x4(uint32_t (&r)[4], uint32_t addr) {
    asm volatile("ldmatrix.sync.aligned.m8n8.x4.shared.b16 {%0,%1,%2,%3}, [%4];"
                 : "=r"(r[0]), "=r"(r[1]), "=r"(r[2]), "=r"(r[3]) : "r"(addr));
}

__device__ __forceinline__ void mma16832_fp8(float (&c)[4], const uint32_t (&a)[4],
                                             uint32_t b0, uint32_t b1) {
    asm volatile(
        "mma.sync.aligned.m16n8k32.row.col.f32.e4m3.e4m3.f32 "
        "{%0,%1,%2,%3}, {%4,%5,%6,%7}, {%8,%9}, {%0,%1,%2,%3};"
        : "+f"(c[0]), "+f"(c[1]), "+f"(c[2]), "+f"(c[3])
        : "r"(a[0]), "r"(a[1]), "r"(a[2]), "r"(a[3]), "r"(b0), "r"(b1));
}

// Pack 4 fp32 -> 4 e4m3 bytes (low->high order e0,e1,e2,e3)
__device__ __forceinline__ uint32_t pack_e4m3_4(float e0, float e1, float e2, float e3) {
    uint16_t lo, hi;
    asm("cvt.rn.satfinite.e4m3x2.f32 %0, %1, %2;" : "=h"(lo) : "f"(e1), "f"(e0));
    asm("cvt.rn.satfinite.e4m3x2.f32 %0, %1, %2;" : "=h"(hi) : "f"(e3), "f"(e2));
    return (uint32_t)lo | ((uint32_t)hi << 16);
}

// ---------------------------------------------------------------------------
// Fused streaming kernel: exp(logits) -> fp8 mma.sync GEMM (deferred softmax
// normalization) -> squared-error reduce.
// Grid: 1024 CTAs x 256 threads (8 warps, 2M x 4N). 2 CTAs per SM.
// ---------------------------------------------------------------------------
__global__ void __launch_bounds__(NTHREADS, 2)
loss_kernel(const float* __restrict__ logits,
            const void*  __restrict__ tgt,
            const float* __restrict__ cb,
            float* __restrict__ out) {
    extern __shared__ char smem[];
    char* Ash = smem;                        // 2 x [64][80B]
    char* Bsh = smem + 2 * A_TILE_B;         // 2 x [256][80B]
    __shared__ float rowinv[M_TILE];
    __shared__ float sred[8];

    const int tid  = threadIdx.x;
    const int lane = tid & 31;
    const int wid  = tid >> 5;
    const int warp_m = wid & 1;    // 0..1
    const int warp_n = wid >> 1;   // 0..3

    // Per-thread logits slice: row = tid>>2 (0..63), quarter q = tid&3.
    const int row = tid >> 2;
    const int q   = tid & 3;
    const float4* src4 = (const float4*)(logits + (size_t)blockIdx.x * M_TILE * VDIM);
    const size_t rowbase4 = (size_t)row * (VDIM / 4);

    const uint32_t a_smem = smem_u32(Ash);
    const uint32_t b_smem = smem_u32(Bsh);

    // ldmatrix source offsets within a buffer (fp8 data viewed as b16 elems):
    // A frag (16 rows x 32 fp8): row = m0 + (lane&15), col byte = (lane>>4)*16
    const uint32_t a_lds_off =
        (uint32_t)((warp_m * 32 + (lane & 15)) * ASTRIDE_B + ((lane >> 4) << 4));
    // B frag (16 n x 32 fp8): row = n0 + (lane&7) + ((lane>>4)<<3),
    //                         col byte = ((lane>>3)&1)*16
    const uint32_t b_lds_off =
        (uint32_t)(((lane & 7) + ((lane >> 4) << 3)) * BSTRIDE_B + (((lane >> 3) & 1) << 4));

    // Prologue: B chunk 0 (256 rows x 64B = 1024 x 16B transfers)
    {
        #pragma unroll
        for (int i = 0; i < 4; i++) {
            int idx = tid + i * NTHREADS;    // 0..1023
            int n   = idx >> 2;
            int kv  = idx & 3;
            cp16(b_smem + n * BSTRIDE_B + kv * 16,
                 g_cbT8 + (size_t)n * VDIM + kv * 16);
        }
        asm volatile("cp.async.commit_group;" ::: "memory");
    }

    float4 cur[4], nxt[4];
    #pragma unroll
    for (int j = 0; j < 4; j++) cur[j] = __ldcs(&src4[rowbase4 + q * 4 + j]);

    float rs = 0.0f;

    float acc[2][8][4];
    #pragma unroll
    for (int mi = 0; mi < 2; mi++)
        #pragma unroll
        for (int nf = 0; nf < 8; nf++)
            #pragma unroll
            for (int x = 0; x < 4; x++) acc[mi][nf][x] = 0.0f;

    #pragma unroll 1
    for (int kc = 0; kc < NCHUNK; kc++) {
        const int buf = kc & 1;

        // Prefetch next logits chunk.
        if (kc + 1 < NCHUNK) {
            #pragma unroll
            for (int j = 0; j < 4; j++)
                nxt[j] = __ldcs(&src4[rowbase4 + (kc + 1) * 16 + q * 4 + j]);
        }

        // exp + rowsum + e4m3 store into A[buf] (16 bytes per thread).
        {
            float e[16];
            #pragma unroll
            for (int j = 0; j < 4; j++) {
                e[j*4+0] = __expf(cur[j].x);
                e[j*4+1] = __expf(cur[j].y);
                e[j*4+2] = __expf(cur[j].z);
                e[j*4+3] = __expf(cur[j].w);
                rs += (e[j*4+0] + e[j*4+1]) + (e[j*4+2] + e[j*4+3]);
            }
            uint4 pk;
            pk.x = pack_e4m3_4(e[0],  e[1],  e[2],  e[3]);
            pk.y = pack_e4m3_4(e[4],  e[5],  e[6],  e[7]);
            pk.z = pack_e4m3_4(e[8],  e[9],  e[10], e[11]);
            pk.w = pack_e4m3_4(e[12], e[13], e[14], e[15]);
            *(uint4*)(Ash + buf * A_TILE_B + row * ASTRIDE_B + q * 16) = pk;
        }

        // B[kc] resident; A stores visible.
        asm volatile("cp.async.wait_group 0;" ::: "memory");
        __syncthreads();

        // Kick off B chunk kc+1 into the other buffer.
        if (kc + 1 < NCHUNK) {
            uint32_t bdst = b_smem + (buf ^ 1) * B_TILE_B;
            #pragma unroll
            for (int i = 0; i < 4; i++) {
                int idx = tid + i * NTHREADS;
                int n   = idx >> 2;
                int kv  = idx & 3;
                cp16(bdst + n * BSTRIDE_B + kv * 16,
                     g_cbT8 + (size_t)n * VDIM + (kc + 1) * KCH + kv * 16);
            }
            asm volatile("cp.async.commit_group;" ::: "memory");
        }

        // MMA: A[64x64 fp8] x B[64x256 fp8], 2 k-steps of 32.
        const uint32_t a_buf = a_smem + buf * A_TILE_B + a_lds_off;
        const uint32_t b_buf = b_smem + buf * B_TILE_B + b_lds_off;

        #pragma unroll
        for (int ks = 0; ks < 2; ks++) {
            uint32_t afr[2][4];
            ldsm_x4(afr[0], a_buf + ks * 32);
            ldsm_x4(afr[1], a_buf + 16 * ASTRIDE_B + ks * 32);
            #pragma unroll
            for (int nb = 0; nb < 4; nb++) {
                uint32_t bfr[4];
                ldsm_x4(bfr, b_buf + (warp_n * 64 + nb * 16) * BSTRIDE_B + ks * 32);
                mma16832_fp8(acc[0][nb * 2 + 0], afr[0], bfr[0], bfr[1]);
                mma16832_fp8(acc[0][nb * 2 + 1], afr[0], bfr[2], bfr[3]);
                mma16832_fp8(acc[1][nb * 2 + 0], afr[1], bfr[0], bfr[1]);
                mma16832_fp8(acc[1][nb * 2 + 1], afr[1], bfr[2], bfr[3]);
            }
        }

        #pragma unroll
        for (int j = 0; j < 4; j++) cur[j] = nxt[j];
    }

    // Row-sum reduce across the 4 threads sharing a row.
    {
        float s = rs;
        s += __shfl_xor_sync(0xffffffffu, s, 1);
        s += __shfl_xor_sync(0xffffffffu, s, 2);
        if (q == 0) rowinv[row] = 1.0f / s;
    }
    __syncthreads();

    // Epilogue: pred = acc * rowinv; loss += (pred - cb[target])^2
    const int is64 = g_tgt64;
    const long long* t64 = (const long long*)tgt;
    const int*       t32 = (const int*)tgt;

    float lsum = 0.0f;
    #pragma unroll
    for (int mi = 0; mi < 2; mi++) {
        int lr0 = warp_m * 32 + mi * 16 + (lane >> 2);
        int lr1 = lr0 + 8;
        int r0 = blockIdx.x * M_TILE + lr0;
        int r1 = blockIdx.x * M_TILE + lr1;
        float inv0 = rowinv[lr0];
        float inv1 = rowinv[lr1];
        int tg0 = is64 ? (int)t64[r0] : t32[r0];
        int tg1 = is64 ? (int)t64[r1] : t32[r1];
        const float* cb0 = cb + (size_t)tg0 * DDIM;
        const float* cb1 = cb + (size_t)tg1 * DDIM;
        #pragma unroll
        for (int nf = 0; nf < 8; nf++) {
            int col = warp_n * 64 + nf * 8 + (lane & 3) * 2;
            float2 g0 = *(const float2*)(cb0 + col);
            float2 g1 = *(const float2*)(cb1 + col);
            float d0 = acc[mi][nf][0] * inv0 - g0.x;
            float d1 = acc[mi][nf][1] * inv0 - g0.y;
            float d2 = acc[mi][nf][2] * inv1 - g1.x;
            float d3 = acc[mi][nf][3] * inv1 - g1.y;
            lsum += d0 * d0 + d1 * d1 + d2 * d2 + d3 * d3;
        }
    }
    #pragma unroll
    for (int off = 16; off > 0; off >>= 1)
        lsum += __shfl_xor_sync(0xffffffffu, lsum, off);

    if (lane == 0) sred[wid] = lsum;
    __syncthreads();
    if (tid == 0) {
        float tot = 0.0f;
        #pragma unroll
        for (int i = 0; i < 8; i++) tot += sred[i];
        atomicAdd(out, tot * (1.0f / ((float)NROWS * (float)DDIM)));
    }
}

// ---------------------------------------------------------------------------
// Launch
// ---------------------------------------------------------------------------
extern "C" void kernel_launch(void* const* d_in, const int* in_sizes, int n_in,
                              void* d_out, int out_size) {
    const float* logits = nullptr;
    const void*  tgt    = nullptr;
    const float* cb     = nullptr;
    for (int i = 0; i < n_in; i++) {
        if (in_sizes[i] == NROWS * VDIM)      logits = (const float*)d_in[i];
        else if (in_sizes[i] == NROWS)        tgt    = d_in[i];
        else if (in_sizes[i] == VDIM * DDIM)  cb     = (const float*)d_in[i];
    }
    float* out = (float*)d_out;

    cudaFuncSetAttribute(loss_kernel,
                         cudaFuncAttributeMaxDynamicSharedMemorySize, SMEM_BYTES);

    dim3 pgrid(VDIM / 32, DDIM / 32);
    dim3 pblk(32, 8);
    prep_kernel<<<pgrid, pblk>>>(cb, tgt, out);

    loss_kernel<<<NCTAS, NTHREADS, SMEM_BYTES>>>(logits, tgt, cb, out);
}